// round 12
// baseline (speedup 1.0000x reference)
#include <cuda_runtime.h>
#include <math.h>

#define BB   8
#define NN   4096
#define TPB  256
#define QPT  4                     // queries per thread
#define QPB  (TPB * QPT)           // 1024 queries per block
#define NQCH (NN / QPB)            // 4 query chunks
#define NTCH 8                     // target chunks
#define TGT  (NN / NTCH)           // 512 targets per block
#define TILE_P (TGT / 2)           // 256 packed target-pairs (8 KB smem)
#define NBLK_TOT (NQCH * BB * 2 * NTCH)   // 512 blocks
#define QTOT (2 * BB * NN)         // 65536 query slots

typedef unsigned long long ull;

// Scratch (__device__ globals; allocation forbidden).
// g_menc holds ~enc_f(min+h) combined via atomicMax. Identity is 0, so the
// runtime's zero-init is valid for call 1, and the tail resets each slot to 0
// after reading -> every graph replay is self-initializing.
__device__ unsigned int g_menc[QTOT];            // 256 KB, zero-init
__device__ unsigned int g_done = 0;

// ---- packed f32x2 helpers (sm_103a) --------------------------------------
__device__ __forceinline__ ull fma2(ull a, ull b, ull c) {
    ull d;
    asm("fma.rn.f32x2 %0, %1, %2, %3;" : "=l"(d) : "l"(a), "l"(b), "l"(c));
    return d;
}
__device__ __forceinline__ ull pack2(float lo, float hi) {
    ull r;
    asm("mov.b64 %0, {%1, %2};" : "=l"(r) : "f"(lo), "f"(hi));
    return r;
}
__device__ __forceinline__ void unpack2(ull v, float& lo, float& hi) {
    asm("mov.b64 {%0, %1}, %2;" : "=f"(lo), "=f"(hi) : "l"(v));
}
// order-preserving float<->uint encode (no NaNs in this workload)
__device__ __forceinline__ unsigned int enc_f(float f) {
    unsigned int u = __float_as_uint(f);
    return ((int)u >= 0) ? (u ^ 0x80000000u) : ~u;
}
__device__ __forceinline__ float dec_f(unsigned int k) {
    return (k & 0x80000000u) ? __uint_as_float(k ^ 0x80000000u)
                             : __uint_as_float(~k);
}

// Compute both relative transforms for batch b into sR/sT (called by 16 thr)
__device__ __forceinline__ void rel_transform_16(
    int tid,
    const float* __restrict__ pred_rot,   const float* __restrict__ pred_trans,
    const float* __restrict__ ctx_hyp_rot,const float* __restrict__ ctx_hyp_trans,
    const float* __restrict__ gt_rot,     const float* __restrict__ gt_trans,
    const float* __restrict__ ctx_gt_rot, const float* __restrict__ ctx_gt_trans,
    float sR[2][BB][9], float sT[2][BB][3])
{
    const int w = tid / BB, b = tid % BB;
    const float* Ra = (w == 0 ? pred_rot      : gt_rot)       + b * 9;
    const float* ta = (w == 0 ? pred_trans    : gt_trans)     + b * 3;
    const float* Rb = (w == 0 ? ctx_hyp_rot   : ctx_gt_rot)   + b * 9;
    const float* tb = (w == 0 ? ctx_hyp_trans : ctx_gt_trans) + b * 3;
    #pragma unroll
    for (int i = 0; i < 3; i++)
        #pragma unroll
        for (int k = 0; k < 3; k++) {
            float s = 0.f;
            #pragma unroll
            for (int j = 0; j < 3; j++) s += Ra[i*3+j] * Rb[k*3+j];
            sR[w][b][i*3+k] = s;
        }
    #pragma unroll
    for (int i = 0; i < 3; i++) {
        float s = ta[i];
        #pragma unroll
        for (int j = 0; j < 3; j++) s -= sR[w][b][i*3+j] * tb[j];
        sT[w][b][i] = s;
    }
}

// ---------------------------------------------------------------------------
// Deterministic block sum reduction (valid in thread 0)
// ---------------------------------------------------------------------------
__device__ __forceinline__ float block_reduce_sum(float v)
{
    __shared__ float ws[TPB / 32];
    #pragma unroll
    for (int o = 16; o > 0; o >>= 1) v += __shfl_down_sync(0xffffffffu, v, o);
    if ((threadIdx.x & 31) == 0) ws[threadIdx.x >> 5] = v;
    __syncthreads();
    if (threadIdx.x < 32) {
        v = (threadIdx.x < TPB / 32) ? ws[threadIdx.x] : 0.f;
        #pragma unroll
        for (int o = 4; o > 0; o >>= 1) v += __shfl_down_sync(0xffffffffu, v, o);
    }
    return v;
}

// ---------------------------------------------------------------------------
// Single fused kernel: self-transforming chamfer + atomicMax min-combine +
// last-done-block final reduce (loss_geo) and parallel loss_trans.
// grid (NQCH=4, BB, 2*NTCH=16) = 512 blocks, 256 thr, QPT=4, lb(256,4).
// ---------------------------------------------------------------------------
__global__ void __launch_bounds__(TPB, 4) k_fused(
    const float* __restrict__ pred_rot,   const float* __restrict__ pred_trans,
    const float* __restrict__ ctx_hyp_rot,const float* __restrict__ ctx_hyp_trans,
    const float* __restrict__ gt_rot,     const float* __restrict__ gt_trans,
    const float* __restrict__ ctx_gt_rot, const float* __restrict__ ctx_gt_trans,
    const float* __restrict__ mp,         float* __restrict__ out)
{
    __shared__ float4 s_xy[TILE_P];
    __shared__ float4 s_zh[TILE_P];
    __shared__ float  s_raw[TGT * 3];          // 6 KB raw target staging
    __shared__ float  sR[2][BB][9];
    __shared__ float  sT[2][BB][3];

    const int dir = blockIdx.z >> 3;
    const int tc  = blockIdx.z & 7;
    const int b   = blockIdx.y;
    const int tid = threadIdx.x;

    if (tid < 2 * BB)
        rel_transform_16(tid, pred_rot, pred_trans, ctx_hyp_rot, ctx_hyp_trans,
                         gt_rot, gt_trans, ctx_gt_rot, ctx_gt_trans, sR, sT);

    // coalesced staging of this block's 512 raw target points (1536 floats)
    {
        const float* src = mp + (b * NN + tc * TGT) * 3;
        #pragma unroll
        for (int i = tid; i < TGT * 3; i += TPB) s_raw[i] = src[i];
    }
    __syncthreads();

    // transform 2 targets per thread into packed tile (w = 1-dir)
    {
        const float* R = sR[1 - dir][b];
        const float* t = sT[1 - dir][b];
        const int p = tid;                      // packed pair index
        float xx[2], yy[2], zz[2], hh[2];
        #pragma unroll
        for (int l = 0; l < 2; l++) {
            const float px = s_raw[(2*p + l)*3 + 0];
            const float py = s_raw[(2*p + l)*3 + 1];
            const float pz = s_raw[(2*p + l)*3 + 2];
            float x = fmaf(R[0], px, fmaf(R[1], py, fmaf(R[2], pz, t[0])));
            float y = fmaf(R[3], px, fmaf(R[4], py, fmaf(R[5], pz, t[1])));
            float z = fmaf(R[6], px, fmaf(R[7], py, fmaf(R[8], pz, t[2])));
            xx[l] = x; yy[l] = y; zz[l] = z;
            hh[l] = 0.5f * fmaf(x, x, fmaf(y, y, z * z));
        }
        s_xy[p] = make_float4(xx[0], xx[1], yy[0], yy[1]);
        s_zh[p] = make_float4(zz[0], zz[1], hh[0], hh[1]);
    }

    // transform 4 queries per thread (w = dir), keep packed-negated + h
    const int nbase = blockIdx.x * QPB + tid;
    ull nx[QPT], ny[QPT], nz[QPT];
    float hq[QPT];
    {
        const float* R = sR[dir][b];
        const float* t = sT[dir][b];
        #pragma unroll
        for (int k = 0; k < QPT; k++) {
            const float* p = mp + (b * NN + nbase + k * TPB) * 3;
            const float px = p[0], py = p[1], pz = p[2];
            float x = fmaf(R[0], px, fmaf(R[1], py, fmaf(R[2], pz, t[0])));
            float y = fmaf(R[3], px, fmaf(R[4], py, fmaf(R[5], pz, t[1])));
            float z = fmaf(R[6], px, fmaf(R[7], py, fmaf(R[8], pz, t[2])));
            hq[k] = 0.5f * fmaf(x, x, fmaf(y, y, z * z));
            nx[k] = pack2(-x, -x);
            ny[k] = pack2(-y, -y);
            nz[k] = pack2(-z, -z);
        }
    }

    float ma[QPT], mb[QPT];
    #pragma unroll
    for (int k = 0; k < QPT; k++) { ma[k] = INFINITY; mb[k] = INFINITY; }

    __syncthreads();

    const ulonglong2* __restrict__ axy = (const ulonglong2*)s_xy;
    const ulonglong2* __restrict__ azh = (const ulonglong2*)s_zh;

    #pragma unroll 4
    for (int j = 0; j < TILE_P; j++) {
        const ulonglong2 A = axy[j];   // (x0,x1) (y0,y1)
        const ulonglong2 B = azh[j];   // (z0,z1) (h0,h1)
        #pragma unroll
        for (int k = 0; k < QPT; k++) {
            ull v = fma2(nz[k], B.x, B.y);
            v = fma2(ny[k], A.y, v);
            v = fma2(nx[k], A.x, v);
            float lo, hi;
            unpack2(v, lo, hi);
            ma[k] = fminf(ma[k], lo);
            mb[k] = fminf(mb[k], hi);
        }
    }

    // exact deterministic min-combine: atomicMax on complement-encoding
    {
        const int db = dir * BB + b;
        #pragma unroll
        for (int k = 0; k < QPT; k++) {
            const unsigned int key = ~enc_f(fminf(ma[k], mb[k]) + hq[k]);
            atomicMax(&g_menc[db * NN + nbase + k * TPB], key);
        }
    }

    // ---- last-done block: final reduce + loss_trans ----
    __shared__ bool is_last;
    __syncthreads();                    // all atomics of this block issued
    if (tid == 0) {
        __threadfence();
        is_last = (atomicAdd(&g_done, 1u) == NBLK_TOT - 1);
    }
    __syncthreads();

    if (is_last) {
        // loss_trans (sR/sT already computed in this block's smem)
        if (tid == 0) {
            float lt = 0.f;
            #pragma unroll
            for (int bb = 0; bb < BB; bb++)
                #pragma unroll
                for (int i = 0; i < 3; i++)
                    lt += fabsf(sT[0][bb][i] - sT[1][bb][i]);
            out[1] = lt * (1.0f / (BB * 3));
        }

        // loss_geo: read all 65536 encoded mins (uint4), decode, sqrt, sum.
        // Reset each slot to 0 (atomicMax identity) for the next replay.
        float s = 0.f;
        uint4* __restrict__ me4 = (uint4*)g_menc;
        for (int i = tid; i < QTOT / 4; i += TPB) {
            const uint4 kv = __ldcg(&me4[i]);
            me4[i] = make_uint4(0u, 0u, 0u, 0u);
            s += sqrtf(fmaxf(2.0f * dec_f(~kv.x), 0.0f));
            s += sqrtf(fmaxf(2.0f * dec_f(~kv.y), 0.0f));
            s += sqrtf(fmaxf(2.0f * dec_f(~kv.z), 0.0f));
            s += sqrtf(fmaxf(2.0f * dec_f(~kv.w), 0.0f));
        }
        float tot = block_reduce_sum(s);
        if (tid == 0) {
            out[0] = tot * (1.0f / (BB * NN));
            __threadfence();
            g_done = 0;   // reset for next graph replay
        }
    }
}

// ---------------------------------------------------------------------------
extern "C" void kernel_launch(void* const* d_in, const int* in_sizes, int n_in,
                              void* d_out, int out_size)
{
    const float* pred_rot      = (const float*)d_in[0];
    const float* pred_trans    = (const float*)d_in[1];
    const float* ctx_hyp_rot   = (const float*)d_in[2];
    const float* ctx_hyp_trans = (const float*)d_in[3];
    const float* gt_rot        = (const float*)d_in[4];
    const float* gt_trans      = (const float*)d_in[5];
    const float* ctx_gt_rot    = (const float*)d_in[6];
    const float* ctx_gt_trans  = (const float*)d_in[7];
    const float* model_points  = (const float*)d_in[8];
    float* out = (float*)d_out;

    k_fused<<<dim3(NQCH, BB, 2 * NTCH), TPB>>>(
        pred_rot, pred_trans, ctx_hyp_rot, ctx_hyp_trans,
        gt_rot, gt_trans, ctx_gt_rot, ctx_gt_trans, model_points, out);
}

// round 13
// speedup vs baseline: 1.5252x; 1.5252x over previous
#include <cuda_runtime.h>
#include <math.h>

#define BB   8
#define NN   4096
#define TPB  256
#define QPT  4                     // queries per thread
#define QPB  (TPB * QPT)           // 1024 queries per block
#define NQCH (NN / QPB)            // 4 query chunks
#define NTCH 8                     // target chunks
#define TGT  (NN / NTCH)           // 512 targets per block
#define TILE_P (TGT / 2)           // 256 packed target-pairs (8 KB smem)
#define NRED_BLK 64
#define QTOT (2 * BB * NN)         // 65536 query slots

typedef unsigned long long ull;

// Scratch (__device__ globals; allocation forbidden).
// g_menc holds ~enc_f(min + h_q), combined via atomicMax (exact, order-
// independent -> deterministic). Identity is 0, so zero-init is valid on the
// first call and k_reduce resets each slot to 0 after reading it -> every
// graph replay is self-initializing. All real keys are > 0.
__device__ unsigned int g_menc[QTOT];            // 256 KB
__device__ float g_partials[NRED_BLK];
__device__ unsigned int g_done = 0;

// ---- packed f32x2 helpers (sm_103a) --------------------------------------
__device__ __forceinline__ ull fma2(ull a, ull b, ull c) {
    ull d;
    asm("fma.rn.f32x2 %0, %1, %2, %3;" : "=l"(d) : "l"(a), "l"(b), "l"(c));
    return d;
}
__device__ __forceinline__ ull pack2(float lo, float hi) {
    ull r;
    asm("mov.b64 %0, {%1, %2};" : "=l"(r) : "f"(lo), "f"(hi));
    return r;
}
__device__ __forceinline__ void unpack2(ull v, float& lo, float& hi) {
    asm("mov.b64 {%0, %1}, %2;" : "=f"(lo), "=f"(hi) : "l"(v));
}
// order-preserving float<->uint encode (no NaNs in this workload)
__device__ __forceinline__ unsigned int enc_f(float f) {
    unsigned int u = __float_as_uint(f);
    return ((int)u >= 0) ? (u ^ 0x80000000u) : ~u;
}
__device__ __forceinline__ float dec_f(unsigned int k) {
    return (k & 0x80000000u) ? __uint_as_float(k ^ 0x80000000u)
                             : __uint_as_float(~k);
}

// Compute both relative transforms for batch b into sR/sT (called by 16 thr)
__device__ __forceinline__ void rel_transform_16(
    int tid,
    const float* __restrict__ pred_rot,   const float* __restrict__ pred_trans,
    const float* __restrict__ ctx_hyp_rot,const float* __restrict__ ctx_hyp_trans,
    const float* __restrict__ gt_rot,     const float* __restrict__ gt_trans,
    const float* __restrict__ ctx_gt_rot, const float* __restrict__ ctx_gt_trans,
    float sR[2][BB][9], float sT[2][BB][3])
{
    const int w = tid / BB, b = tid % BB;
    const float* Ra = (w == 0 ? pred_rot      : gt_rot)       + b * 9;
    const float* ta = (w == 0 ? pred_trans    : gt_trans)     + b * 3;
    const float* Rb = (w == 0 ? ctx_hyp_rot   : ctx_gt_rot)   + b * 9;
    const float* tb = (w == 0 ? ctx_hyp_trans : ctx_gt_trans) + b * 3;
    #pragma unroll
    for (int i = 0; i < 3; i++)
        #pragma unroll
        for (int k = 0; k < 3; k++) {
            float s = 0.f;
            #pragma unroll
            for (int j = 0; j < 3; j++) s += Ra[i*3+j] * Rb[k*3+j];
            sR[w][b][i*3+k] = s;
        }
    #pragma unroll
    for (int i = 0; i < 3; i++) {
        float s = ta[i];
        #pragma unroll
        for (int j = 0; j < 3; j++) s -= sR[w][b][i*3+j] * tb[j];
        sT[w][b][i] = s;
    }
}

// ---------------------------------------------------------------------------
// Kernel 1: self-transforming chamfer (hot path identical to R11).
// grid (4, 8, 16) = 512 blocks, 256 thr, QPT=4, lb(256,4).
// Final combine: atomicMax on complement-encoded (min + h_q).
// ---------------------------------------------------------------------------
__global__ void __launch_bounds__(TPB, 4) k_chamfer(
    const float* __restrict__ pred_rot,   const float* __restrict__ pred_trans,
    const float* __restrict__ ctx_hyp_rot,const float* __restrict__ ctx_hyp_trans,
    const float* __restrict__ gt_rot,     const float* __restrict__ gt_trans,
    const float* __restrict__ ctx_gt_rot, const float* __restrict__ ctx_gt_trans,
    const float* __restrict__ mp)
{
    __shared__ float4 s_xy[TILE_P];
    __shared__ float4 s_zh[TILE_P];
    __shared__ float  s_raw[TGT * 3];          // 6 KB raw target staging
    __shared__ float  sR[2][BB][9];
    __shared__ float  sT[2][BB][3];

    const int dir = blockIdx.z >> 3;
    const int tc  = blockIdx.z & 7;
    const int b   = blockIdx.y;
    const int tid = threadIdx.x;

    if (tid < 2 * BB)
        rel_transform_16(tid, pred_rot, pred_trans, ctx_hyp_rot, ctx_hyp_trans,
                         gt_rot, gt_trans, ctx_gt_rot, ctx_gt_trans, sR, sT);

    // coalesced staging of this block's 512 raw target points (1536 floats)
    {
        const float* src = mp + (b * NN + tc * TGT) * 3;
        #pragma unroll
        for (int i = tid; i < TGT * 3; i += TPB) s_raw[i] = src[i];
    }
    __syncthreads();

    // transform 2 targets per thread into packed tile (w = 1-dir)
    {
        const float* R = sR[1 - dir][b];
        const float* t = sT[1 - dir][b];
        const int p = tid;                      // packed pair index
        float xx[2], yy[2], zz[2], hh[2];
        #pragma unroll
        for (int l = 0; l < 2; l++) {
            const float px = s_raw[(2*p + l)*3 + 0];
            const float py = s_raw[(2*p + l)*3 + 1];
            const float pz = s_raw[(2*p + l)*3 + 2];
            float x = fmaf(R[0], px, fmaf(R[1], py, fmaf(R[2], pz, t[0])));
            float y = fmaf(R[3], px, fmaf(R[4], py, fmaf(R[5], pz, t[1])));
            float z = fmaf(R[6], px, fmaf(R[7], py, fmaf(R[8], pz, t[2])));
            xx[l] = x; yy[l] = y; zz[l] = z;
            hh[l] = 0.5f * fmaf(x, x, fmaf(y, y, z * z));
        }
        s_xy[p] = make_float4(xx[0], xx[1], yy[0], yy[1]);
        s_zh[p] = make_float4(zz[0], zz[1], hh[0], hh[1]);
    }

    // transform 4 queries per thread (w = dir), keep packed-negated + h
    const int nbase = blockIdx.x * QPB + tid;
    ull nx[QPT], ny[QPT], nz[QPT];
    float hq[QPT];
    {
        const float* R = sR[dir][b];
        const float* t = sT[dir][b];
        #pragma unroll
        for (int k = 0; k < QPT; k++) {
            const float* p = mp + (b * NN + nbase + k * TPB) * 3;
            const float px = p[0], py = p[1], pz = p[2];
            float x = fmaf(R[0], px, fmaf(R[1], py, fmaf(R[2], pz, t[0])));
            float y = fmaf(R[3], px, fmaf(R[4], py, fmaf(R[5], pz, t[1])));
            float z = fmaf(R[6], px, fmaf(R[7], py, fmaf(R[8], pz, t[2])));
            hq[k] = 0.5f * fmaf(x, x, fmaf(y, y, z * z));
            nx[k] = pack2(-x, -x);
            ny[k] = pack2(-y, -y);
            nz[k] = pack2(-z, -z);
        }
    }

    float ma[QPT], mb[QPT];
    #pragma unroll
    for (int k = 0; k < QPT; k++) { ma[k] = INFINITY; mb[k] = INFINITY; }

    __syncthreads();

    const ulonglong2* __restrict__ axy = (const ulonglong2*)s_xy;
    const ulonglong2* __restrict__ azh = (const ulonglong2*)s_zh;

    #pragma unroll 4
    for (int j = 0; j < TILE_P; j++) {
        const ulonglong2 A = axy[j];   // (x0,x1) (y0,y1)
        const ulonglong2 B = azh[j];   // (z0,z1) (h0,h1)
        #pragma unroll
        for (int k = 0; k < QPT; k++) {
            ull v = fma2(nz[k], B.x, B.y);
            v = fma2(ny[k], A.y, v);
            v = fma2(nx[k], A.x, v);
            float lo, hi;
            unpack2(v, lo, hi);
            ma[k] = fminf(ma[k], lo);
            mb[k] = fminf(mb[k], hi);
        }
    }

    // exact deterministic min-combine: atomicMax on complement-encoding
    {
        const int db = dir * BB + b;
        #pragma unroll
        for (int k = 0; k < QPT; k++) {
            const unsigned int key = ~enc_f(fminf(ma[k], mb[k]) + hq[k]);
            atomicMax(&g_menc[db * NN + nbase + k * TPB], key);
        }
    }
}

// ---------------------------------------------------------------------------
// Deterministic block sum reduction (valid in thread 0)
// ---------------------------------------------------------------------------
__device__ __forceinline__ float block_reduce_sum(float v)
{
    __shared__ float ws[TPB / 32];
    #pragma unroll
    for (int o = 16; o > 0; o >>= 1) v += __shfl_down_sync(0xffffffffu, v, o);
    if ((threadIdx.x & 31) == 0) ws[threadIdx.x >> 5] = v;
    __syncthreads();
    if (threadIdx.x < 32) {
        v = (threadIdx.x < TPB / 32) ? ws[threadIdx.x] : 0.f;
        #pragma unroll
        for (int o = 4; o > 0; o >>= 1) v += __shfl_down_sync(0xffffffffu, v, o);
    }
    return v;
}

// ---------------------------------------------------------------------------
// Kernel 2 (PDL secondary): loss_trans BEFORE the grid-dependency sync
// (independent of chamfer), then read+reset g_menc (one uint4/thread),
// deferred sqrt, fixed-order final sum in the last-done block.
// ---------------------------------------------------------------------------
__global__ void __launch_bounds__(TPB) k_reduce(
    const float* __restrict__ pred_rot,   const float* __restrict__ pred_trans,
    const float* __restrict__ ctx_hyp_rot,const float* __restrict__ ctx_hyp_trans,
    const float* __restrict__ gt_rot,     const float* __restrict__ gt_trans,
    const float* __restrict__ ctx_gt_rot, const float* __restrict__ ctx_gt_trans,
    float* __restrict__ out)
{
    const int tid = threadIdx.x;

    // independent preamble: loss_trans in block 0 (overlaps chamfer tail)
    __shared__ float sR[2][BB][9];
    __shared__ float sT[2][BB][3];
    if (blockIdx.x == 0) {
        if (tid < 2 * BB)
            rel_transform_16(tid, pred_rot, pred_trans, ctx_hyp_rot, ctx_hyp_trans,
                             gt_rot, gt_trans, ctx_gt_rot, ctx_gt_trans, sR, sT);
        __syncthreads();
        if (tid == 0) {
            float lt = 0.f;
            #pragma unroll
            for (int bb = 0; bb < BB; bb++)
                #pragma unroll
                for (int i = 0; i < 3; i++)
                    lt += fabsf(sT[0][bb][i] - sT[1][bb][i]);
            out[1] = lt * (1.0f / (BB * 3));
        }
    }

    // wait for chamfer's writes to be visible
    cudaGridDependencySynchronize();

    // one uint4 per thread: 64 blk * 256 thr * 4 = 65536 slots
    const int i = blockIdx.x * TPB + tid;
    uint4* __restrict__ me4 = (uint4*)g_menc;
    const uint4 kv = __ldcg(&me4[i]);
    me4[i] = make_uint4(0u, 0u, 0u, 0u);     // reset for next replay
    float s = sqrtf(fmaxf(2.0f * dec_f(~kv.x), 0.0f))
            + sqrtf(fmaxf(2.0f * dec_f(~kv.y), 0.0f))
            + sqrtf(fmaxf(2.0f * dec_f(~kv.z), 0.0f))
            + sqrtf(fmaxf(2.0f * dec_f(~kv.w), 0.0f));

    float bs = block_reduce_sum(s);

    __shared__ bool is_last;
    if (tid == 0) {
        g_partials[blockIdx.x] = bs;
        __threadfence();
        is_last = (atomicAdd(&g_done, 1u) == NRED_BLK - 1);
    }
    __syncthreads();

    if (is_last) {
        const volatile float* vp = g_partials;
        float v = (tid < NRED_BLK) ? vp[tid] : 0.f;
        float tot = block_reduce_sum(v);
        if (tid == 0) {
            out[0] = tot * (1.0f / (BB * NN));
            g_done = 0;   // reset for next graph replay
        }
    }
}

// ---------------------------------------------------------------------------
extern "C" void kernel_launch(void* const* d_in, const int* in_sizes, int n_in,
                              void* d_out, int out_size)
{
    const float* pred_rot      = (const float*)d_in[0];
    const float* pred_trans    = (const float*)d_in[1];
    const float* ctx_hyp_rot   = (const float*)d_in[2];
    const float* ctx_hyp_trans = (const float*)d_in[3];
    const float* gt_rot        = (const float*)d_in[4];
    const float* gt_trans      = (const float*)d_in[5];
    const float* ctx_gt_rot    = (const float*)d_in[6];
    const float* ctx_gt_trans  = (const float*)d_in[7];
    const float* model_points  = (const float*)d_in[8];
    float* out = (float*)d_out;

    k_chamfer<<<dim3(NQCH, BB, 2 * NTCH), TPB>>>(
        pred_rot, pred_trans, ctx_hyp_rot, ctx_hyp_trans,
        gt_rot, gt_trans, ctx_gt_rot, ctx_gt_trans, model_points);

    // PDL launch: overlap reduce's launch + loss_trans with the chamfer tail
    cudaLaunchConfig_t cfg = {};
    cfg.gridDim  = dim3(NRED_BLK, 1, 1);
    cfg.blockDim = dim3(TPB, 1, 1);
    cfg.dynamicSmemBytes = 0;
    cfg.stream = 0;
    cudaLaunchAttribute attrs[1];
    attrs[0].id = cudaLaunchAttributeProgrammaticStreamSerialization;
    attrs[0].val.programmaticStreamSerializationAllowed = 1;
    cfg.attrs = attrs;
    cfg.numAttrs = 1;
    cudaLaunchKernelEx(&cfg, k_reduce,
                       pred_rot, pred_trans, ctx_hyp_rot, ctx_hyp_trans,
                       gt_rot, gt_trans, ctx_gt_rot, ctx_gt_trans, out);
}

// round 14
// speedup vs baseline: 1.6669x; 1.0929x over previous
#include <cuda_runtime.h>
#include <math.h>

#define BB   8
#define NN   4096
#define TPB  256
#define QPT  4                     // queries per thread
#define QPB  (TPB * QPT)           // 1024 queries per block
#define NQCH (NN / QPB)            // 4 query chunks
#define NTCH 16                    // target chunks
#define TGT  (NN / NTCH)           // 256 targets per block
#define TILE_P (TGT / 2)           // 128 packed target-pairs (4 KB smem)
#define NRED_BLK 64
#define QTOT (2 * BB * NN)         // 65536 query slots

typedef unsigned long long ull;

// Scratch (__device__ globals; allocation forbidden).
// g_menc holds ~enc_f(min + h_q), combined via atomicMax (exact, order-
// independent -> deterministic). Identity is 0: zero-init is valid on call 1
// and k_reduce resets each slot to 0 after reading -> self-initializing
// on every graph replay. All real keys are > 0.
__device__ unsigned int g_menc[QTOT];            // 256 KB
__device__ float g_partials[NRED_BLK];
__device__ unsigned int g_done = 0;

// ---- packed f32x2 helpers (sm_103a) --------------------------------------
__device__ __forceinline__ ull fma2(ull a, ull b, ull c) {
    ull d;
    asm("fma.rn.f32x2 %0, %1, %2, %3;" : "=l"(d) : "l"(a), "l"(b), "l"(c));
    return d;
}
__device__ __forceinline__ ull pack2(float lo, float hi) {
    ull r;
    asm("mov.b64 %0, {%1, %2};" : "=l"(r) : "f"(lo), "f"(hi));
    return r;
}
__device__ __forceinline__ void unpack2(ull v, float& lo, float& hi) {
    asm("mov.b64 {%0, %1}, %2;" : "=f"(lo), "=f"(hi) : "l"(v));
}
// order-preserving float<->uint encode (no NaNs in this workload)
__device__ __forceinline__ unsigned int enc_f(float f) {
    unsigned int u = __float_as_uint(f);
    return ((int)u >= 0) ? (u ^ 0x80000000u) : ~u;
}
__device__ __forceinline__ float dec_f(unsigned int k) {
    return (k & 0x80000000u) ? __uint_as_float(k ^ 0x80000000u)
                             : __uint_as_float(~k);
}

// Compute both relative transforms for batch b into sR/sT (called by 16 thr)
__device__ __forceinline__ void rel_transform_16(
    int tid,
    const float* __restrict__ pred_rot,   const float* __restrict__ pred_trans,
    const float* __restrict__ ctx_hyp_rot,const float* __restrict__ ctx_hyp_trans,
    const float* __restrict__ gt_rot,     const float* __restrict__ gt_trans,
    const float* __restrict__ ctx_gt_rot, const float* __restrict__ ctx_gt_trans,
    float sR[2][BB][9], float sT[2][BB][3])
{
    const int w = tid / BB, b = tid % BB;
    const float* Ra = (w == 0 ? pred_rot      : gt_rot)       + b * 9;
    const float* ta = (w == 0 ? pred_trans    : gt_trans)     + b * 3;
    const float* Rb = (w == 0 ? ctx_hyp_rot   : ctx_gt_rot)   + b * 9;
    const float* tb = (w == 0 ? ctx_hyp_trans : ctx_gt_trans) + b * 3;
    #pragma unroll
    for (int i = 0; i < 3; i++)
        #pragma unroll
        for (int k = 0; k < 3; k++) {
            float s = 0.f;
            #pragma unroll
            for (int j = 0; j < 3; j++) s += Ra[i*3+j] * Rb[k*3+j];
            sR[w][b][i*3+k] = s;
        }
    #pragma unroll
    for (int i = 0; i < 3; i++) {
        float s = ta[i];
        #pragma unroll
        for (int j = 0; j < 3; j++) s -= sR[w][b][i*3+j] * tb[j];
        sT[w][b][i] = s;
    }
}

// ---------------------------------------------------------------------------
// Kernel 1: self-transforming chamfer. grid (4, 8, 32) = 1024 blocks,
// 256 thr, QPT=4, lb(256,4). 1024 blocks / 592 residency slots -> HW
// scheduler self-balances; CTA-count quantization loss drops 15.6% -> ~1%.
// Hot loop + atomicMax combine identical to R13.
// ---------------------------------------------------------------------------
__global__ void __launch_bounds__(TPB, 4) k_chamfer(
    const float* __restrict__ pred_rot,   const float* __restrict__ pred_trans,
    const float* __restrict__ ctx_hyp_rot,const float* __restrict__ ctx_hyp_trans,
    const float* __restrict__ gt_rot,     const float* __restrict__ gt_trans,
    const float* __restrict__ ctx_gt_rot, const float* __restrict__ ctx_gt_trans,
    const float* __restrict__ mp)
{
    __shared__ float4 s_xy[TILE_P];
    __shared__ float4 s_zh[TILE_P];
    __shared__ float  s_raw[TGT * 3];          // 3 KB raw target staging
    __shared__ float  sR[2][BB][9];
    __shared__ float  sT[2][BB][3];

    const int dir = blockIdx.z >> 4;
    const int tc  = blockIdx.z & 15;
    const int b   = blockIdx.y;
    const int tid = threadIdx.x;

    if (tid < 2 * BB)
        rel_transform_16(tid, pred_rot, pred_trans, ctx_hyp_rot, ctx_hyp_trans,
                         gt_rot, gt_trans, ctx_gt_rot, ctx_gt_trans, sR, sT);

    // coalesced staging of this block's 256 raw target points (768 floats)
    {
        const float* src = mp + (b * NN + tc * TGT) * 3;
        #pragma unroll
        for (int i = tid; i < TGT * 3; i += TPB) s_raw[i] = src[i];
    }
    __syncthreads();

    // transform 2 targets per thread into packed tile (w = 1-dir)
    if (tid < TILE_P) {
        const float* R = sR[1 - dir][b];
        const float* t = sT[1 - dir][b];
        const int p = tid;                      // packed pair index
        float xx[2], yy[2], zz[2], hh[2];
        #pragma unroll
        for (int l = 0; l < 2; l++) {
            const float px = s_raw[(2*p + l)*3 + 0];
            const float py = s_raw[(2*p + l)*3 + 1];
            const float pz = s_raw[(2*p + l)*3 + 2];
            float x = fmaf(R[0], px, fmaf(R[1], py, fmaf(R[2], pz, t[0])));
            float y = fmaf(R[3], px, fmaf(R[4], py, fmaf(R[5], pz, t[1])));
            float z = fmaf(R[6], px, fmaf(R[7], py, fmaf(R[8], pz, t[2])));
            xx[l] = x; yy[l] = y; zz[l] = z;
            hh[l] = 0.5f * fmaf(x, x, fmaf(y, y, z * z));
        }
        s_xy[p] = make_float4(xx[0], xx[1], yy[0], yy[1]);
        s_zh[p] = make_float4(zz[0], zz[1], hh[0], hh[1]);
    }

    // transform 4 queries per thread (w = dir), keep packed-negated + h
    const int nbase = blockIdx.x * QPB + tid;
    ull nx[QPT], ny[QPT], nz[QPT];
    float hq[QPT];
    {
        const float* R = sR[dir][b];
        const float* t = sT[dir][b];
        #pragma unroll
        for (int k = 0; k < QPT; k++) {
            const float* p = mp + (b * NN + nbase + k * TPB) * 3;
            const float px = p[0], py = p[1], pz = p[2];
            float x = fmaf(R[0], px, fmaf(R[1], py, fmaf(R[2], pz, t[0])));
            float y = fmaf(R[3], px, fmaf(R[4], py, fmaf(R[5], pz, t[1])));
            float z = fmaf(R[6], px, fmaf(R[7], py, fmaf(R[8], pz, t[2])));
            hq[k] = 0.5f * fmaf(x, x, fmaf(y, y, z * z));
            nx[k] = pack2(-x, -x);
            ny[k] = pack2(-y, -y);
            nz[k] = pack2(-z, -z);
        }
    }

    float ma[QPT], mb[QPT];
    #pragma unroll
    for (int k = 0; k < QPT; k++) { ma[k] = INFINITY; mb[k] = INFINITY; }

    __syncthreads();

    const ulonglong2* __restrict__ axy = (const ulonglong2*)s_xy;
    const ulonglong2* __restrict__ azh = (const ulonglong2*)s_zh;

    #pragma unroll 4
    for (int j = 0; j < TILE_P; j++) {
        const ulonglong2 A = axy[j];   // (x0,x1) (y0,y1)
        const ulonglong2 B = azh[j];   // (z0,z1) (h0,h1)
        #pragma unroll
        for (int k = 0; k < QPT; k++) {
            ull v = fma2(nz[k], B.x, B.y);
            v = fma2(ny[k], A.y, v);
            v = fma2(nx[k], A.x, v);
            float lo, hi;
            unpack2(v, lo, hi);
            ma[k] = fminf(ma[k], lo);
            mb[k] = fminf(mb[k], hi);
        }
    }

    // exact deterministic min-combine: atomicMax on complement-encoding
    {
        const int db = dir * BB + b;
        #pragma unroll
        for (int k = 0; k < QPT; k++) {
            const unsigned int key = ~enc_f(fminf(ma[k], mb[k]) + hq[k]);
            atomicMax(&g_menc[db * NN + nbase + k * TPB], key);
        }
    }
}

// ---------------------------------------------------------------------------
// Deterministic block sum reduction (valid in thread 0)
// ---------------------------------------------------------------------------
__device__ __forceinline__ float block_reduce_sum(float v)
{
    __shared__ float ws[TPB / 32];
    #pragma unroll
    for (int o = 16; o > 0; o >>= 1) v += __shfl_down_sync(0xffffffffu, v, o);
    if ((threadIdx.x & 31) == 0) ws[threadIdx.x >> 5] = v;
    __syncthreads();
    if (threadIdx.x < 32) {
        v = (threadIdx.x < TPB / 32) ? ws[threadIdx.x] : 0.f;
        #pragma unroll
        for (int o = 4; o > 0; o >>= 1) v += __shfl_down_sync(0xffffffffu, v, o);
    }
    return v;
}

// ---------------------------------------------------------------------------
// Kernel 2 (PDL secondary): loss_trans BEFORE the grid-dependency sync,
// then read+reset g_menc (one uint4/thread), deferred sqrt, fixed-order
// final sum in the last-done block.
// ---------------------------------------------------------------------------
__global__ void __launch_bounds__(TPB) k_reduce(
    const float* __restrict__ pred_rot,   const float* __restrict__ pred_trans,
    const float* __restrict__ ctx_hyp_rot,const float* __restrict__ ctx_hyp_trans,
    const float* __restrict__ gt_rot,     const float* __restrict__ gt_trans,
    const float* __restrict__ ctx_gt_rot, const float* __restrict__ ctx_gt_trans,
    float* __restrict__ out)
{
    const int tid = threadIdx.x;

    // independent preamble: loss_trans in block 0 (overlaps chamfer tail)
    __shared__ float sR[2][BB][9];
    __shared__ float sT[2][BB][3];
    if (blockIdx.x == 0) {
        if (tid < 2 * BB)
            rel_transform_16(tid, pred_rot, pred_trans, ctx_hyp_rot, ctx_hyp_trans,
                             gt_rot, gt_trans, ctx_gt_rot, ctx_gt_trans, sR, sT);
        __syncthreads();
        if (tid == 0) {
            float lt = 0.f;
            #pragma unroll
            for (int bb = 0; bb < BB; bb++)
                #pragma unroll
                for (int i = 0; i < 3; i++)
                    lt += fabsf(sT[0][bb][i] - sT[1][bb][i]);
            out[1] = lt * (1.0f / (BB * 3));
        }
    }

    // wait for chamfer's writes to be visible
    cudaGridDependencySynchronize();

    // one uint4 per thread: 64 blk * 256 thr * 4 = 65536 slots
    const int i = blockIdx.x * TPB + tid;
    uint4* __restrict__ me4 = (uint4*)g_menc;
    const uint4 kv = __ldcg(&me4[i]);
    me4[i] = make_uint4(0u, 0u, 0u, 0u);     // reset for next replay
    float s = sqrtf(fmaxf(2.0f * dec_f(~kv.x), 0.0f))
            + sqrtf(fmaxf(2.0f * dec_f(~kv.y), 0.0f))
            + sqrtf(fmaxf(2.0f * dec_f(~kv.z), 0.0f))
            + sqrtf(fmaxf(2.0f * dec_f(~kv.w), 0.0f));

    float bs = block_reduce_sum(s);

    __shared__ bool is_last;
    if (tid == 0) {
        g_partials[blockIdx.x] = bs;
        __threadfence();
        is_last = (atomicAdd(&g_done, 1u) == NRED_BLK - 1);
    }
    __syncthreads();

    if (is_last) {
        const volatile float* vp = g_partials;
        float v = (tid < NRED_BLK) ? vp[tid] : 0.f;
        float tot = block_reduce_sum(v);
        if (tid == 0) {
            out[0] = tot * (1.0f / (BB * NN));
            g_done = 0;   // reset for next graph replay
        }
    }
}

// ---------------------------------------------------------------------------
extern "C" void kernel_launch(void* const* d_in, const int* in_sizes, int n_in,
                              void* d_out, int out_size)
{
    const float* pred_rot      = (const float*)d_in[0];
    const float* pred_trans    = (const float*)d_in[1];
    const float* ctx_hyp_rot   = (const float*)d_in[2];
    const float* ctx_hyp_trans = (const float*)d_in[3];
    const float* gt_rot        = (const float*)d_in[4];
    const float* gt_trans      = (const float*)d_in[5];
    const float* ctx_gt_rot    = (const float*)d_in[6];
    const float* ctx_gt_trans  = (const float*)d_in[7];
    const float* model_points  = (const float*)d_in[8];
    float* out = (float*)d_out;

    k_chamfer<<<dim3(NQCH, BB, 2 * NTCH), TPB>>>(
        pred_rot, pred_trans, ctx_hyp_rot, ctx_hyp_trans,
        gt_rot, gt_trans, ctx_gt_rot, ctx_gt_trans, model_points);

    // PDL launch: overlap reduce's launch + loss_trans with the chamfer tail
    cudaLaunchConfig_t cfg = {};
    cfg.gridDim  = dim3(NRED_BLK, 1, 1);
    cfg.blockDim = dim3(TPB, 1, 1);
    cfg.dynamicSmemBytes = 0;
    cfg.stream = 0;
    cudaLaunchAttribute attrs[1];
    attrs[0].id = cudaLaunchAttributeProgrammaticStreamSerialization;
    attrs[0].val.programmaticStreamSerializationAllowed = 1;
    cfg.attrs = attrs;
    cfg.numAttrs = 1;
    cudaLaunchKernelEx(&cfg, k_reduce,
                       pred_rot, pred_trans, ctx_hyp_rot, ctx_hyp_trans,
                       gt_rot, gt_trans, ctx_gt_rot, ctx_gt_trans, out);
}

// round 15
// speedup vs baseline: 1.6763x; 1.0056x over previous
#include <cuda_runtime.h>
#include <math.h>

#define BB   8
#define NN   4096
#define TPB  256
#define QPT  4                     // queries per thread
#define QPB  (TPB * QPT)           // 1024 queries per item
#define NQCH (NN / QPB)            // 4 query chunks
#define NTCH 16                    // target chunks
#define TGT  (NN / NTCH)           // 256 targets per item
#define TILE_P (TGT / 2)           // 128 packed target-pairs (4 KB smem)
#define NITEMS (2 * BB * NQCH * NTCH)   // 1024 work items
#define NBLK_CH 444                // persistent chamfer blocks (3 per SM)
#define NRED_BLK 64
#define QTOT (2 * BB * NN)         // 65536 query slots

typedef unsigned long long ull;

// Scratch (__device__ globals; allocation forbidden).
// g_menc holds ~enc_f(min + h_q), combined via atomicMax (exact, order-
// independent -> deterministic). Identity is 0: zero-init is valid on call 1
// and k_reduce resets each slot to 0 after reading -> self-initializing
// on every graph replay. All real keys are > 0. g_work/g_done likewise reset
// by k_reduce each replay.
__device__ unsigned int g_menc[QTOT];            // 256 KB
__device__ float g_partials[NRED_BLK];
__device__ unsigned int g_work = 0;
__device__ unsigned int g_done = 0;

// ---- packed f32x2 helpers (sm_103a) --------------------------------------
__device__ __forceinline__ ull fma2(ull a, ull b, ull c) {
    ull d;
    asm("fma.rn.f32x2 %0, %1, %2, %3;" : "=l"(d) : "l"(a), "l"(b), "l"(c));
    return d;
}
__device__ __forceinline__ ull pack2(float lo, float hi) {
    ull r;
    asm("mov.b64 %0, {%1, %2};" : "=l"(r) : "f"(lo), "f"(hi));
    return r;
}
__device__ __forceinline__ void unpack2(ull v, float& lo, float& hi) {
    asm("mov.b64 {%0, %1}, %2;" : "=f"(lo), "=f"(hi) : "l"(v));
}
// order-preserving float<->uint encode (no NaNs in this workload)
__device__ __forceinline__ unsigned int enc_f(float f) {
    unsigned int u = __float_as_uint(f);
    return ((int)u >= 0) ? (u ^ 0x80000000u) : ~u;
}
__device__ __forceinline__ float dec_f(unsigned int k) {
    return (k & 0x80000000u) ? __uint_as_float(k ^ 0x80000000u)
                             : __uint_as_float(~k);
}

// Compute both relative transforms for batch b into sR/sT (called by 16 thr)
__device__ __forceinline__ void rel_transform_16(
    int tid,
    const float* __restrict__ pred_rot,   const float* __restrict__ pred_trans,
    const float* __restrict__ ctx_hyp_rot,const float* __restrict__ ctx_hyp_trans,
    const float* __restrict__ gt_rot,     const float* __restrict__ gt_trans,
    const float* __restrict__ ctx_gt_rot, const float* __restrict__ ctx_gt_trans,
    float sR[2][BB][9], float sT[2][BB][3])
{
    const int w = tid / BB, b = tid % BB;
    const float* Ra = (w == 0 ? pred_rot      : gt_rot)       + b * 9;
    const float* ta = (w == 0 ? pred_trans    : gt_trans)     + b * 3;
    const float* Rb = (w == 0 ? ctx_hyp_rot   : ctx_gt_rot)   + b * 9;
    const float* tb = (w == 0 ? ctx_hyp_trans : ctx_gt_trans) + b * 3;
    #pragma unroll
    for (int i = 0; i < 3; i++)
        #pragma unroll
        for (int k = 0; k < 3; k++) {
            float s = 0.f;
            #pragma unroll
            for (int j = 0; j < 3; j++) s += Ra[i*3+j] * Rb[k*3+j];
            sR[w][b][i*3+k] = s;
        }
    #pragma unroll
    for (int i = 0; i < 3; i++) {
        float s = ta[i];
        #pragma unroll
        for (int j = 0; j < 3; j++) s -= sR[w][b][i*3+j] * tb[j];
        sT[w][b][i] = s;
    }
}

// ---------------------------------------------------------------------------
// Kernel 1: persistent work-stealing chamfer. 444 blocks (3/SM, lb(256,3)
// -> 85-reg budget, no spill cliff) steal 1024 items; each item is exactly
// an R14 block (1024 queries x 256 targets, packed-f32x2 core, atomicMax
// combine). Kills the 13.5% CTA-wave quantization: tail <= 1 item.
// Rel transforms computed once per block (item-invariant).
// ---------------------------------------------------------------------------
__global__ void __launch_bounds__(TPB, 3) k_chamfer(
    const float* __restrict__ pred_rot,   const float* __restrict__ pred_trans,
    const float* __restrict__ ctx_hyp_rot,const float* __restrict__ ctx_hyp_trans,
    const float* __restrict__ gt_rot,     const float* __restrict__ gt_trans,
    const float* __restrict__ ctx_gt_rot, const float* __restrict__ ctx_gt_trans,
    const float* __restrict__ mp)
{
    __shared__ float4 s_xy[TILE_P];
    __shared__ float4 s_zh[TILE_P];
    __shared__ float  s_raw[TGT * 3];          // 3 KB raw target staging
    __shared__ float  sR[2][BB][9];
    __shared__ float  sT[2][BB][3];
    __shared__ int    s_item;

    const int tid = threadIdx.x;

    if (tid < 2 * BB)
        rel_transform_16(tid, pred_rot, pred_trans, ctx_hyp_rot, ctx_hyp_trans,
                         gt_rot, gt_trans, ctx_gt_rot, ctx_gt_trans, sR, sT);
    // sR/sT visibility is covered by the first in-loop __syncthreads below.

    for (;;) {
        if (tid == 0) s_item = (int)atomicAdd(&g_work, 1u);
        __syncthreads();               // item ready; prev item fully done
        const int item = s_item;
        if (item >= NITEMS) break;

        const int tc  = item & (NTCH - 1);
        const int qc  = (item >> 4) & (NQCH - 1);
        const int b   = (item >> 6) & (BB - 1);
        const int dir = item >> 9;

        // coalesced staging of this item's 256 raw target points
        {
            const float* src = mp + (b * NN + tc * TGT) * 3;
            #pragma unroll
            for (int i = tid; i < TGT * 3; i += TPB) s_raw[i] = src[i];
        }
        __syncthreads();

        // transform 2 targets per thread into packed tile (w = 1-dir)
        if (tid < TILE_P) {
            const float* R = sR[1 - dir][b];
            const float* t = sT[1 - dir][b];
            const int p = tid;                  // packed pair index
            float xx[2], yy[2], zz[2], hh[2];
            #pragma unroll
            for (int l = 0; l < 2; l++) {
                const float px = s_raw[(2*p + l)*3 + 0];
                const float py = s_raw[(2*p + l)*3 + 1];
                const float pz = s_raw[(2*p + l)*3 + 2];
                float x = fmaf(R[0], px, fmaf(R[1], py, fmaf(R[2], pz, t[0])));
                float y = fmaf(R[3], px, fmaf(R[4], py, fmaf(R[5], pz, t[1])));
                float z = fmaf(R[6], px, fmaf(R[7], py, fmaf(R[8], pz, t[2])));
                xx[l] = x; yy[l] = y; zz[l] = z;
                hh[l] = 0.5f * fmaf(x, x, fmaf(y, y, z * z));
            }
            s_xy[p] = make_float4(xx[0], xx[1], yy[0], yy[1]);
            s_zh[p] = make_float4(zz[0], zz[1], hh[0], hh[1]);
        }

        // transform 4 queries per thread (w = dir), packed-negated + h
        const int nbase = qc * QPB + tid;
        ull nx[QPT], ny[QPT], nz[QPT];
        float hq[QPT];
        {
            const float* R = sR[dir][b];
            const float* t = sT[dir][b];
            #pragma unroll
            for (int k = 0; k < QPT; k++) {
                const float* p = mp + (b * NN + nbase + k * TPB) * 3;
                const float px = p[0], py = p[1], pz = p[2];
                float x = fmaf(R[0], px, fmaf(R[1], py, fmaf(R[2], pz, t[0])));
                float y = fmaf(R[3], px, fmaf(R[4], py, fmaf(R[5], pz, t[1])));
                float z = fmaf(R[6], px, fmaf(R[7], py, fmaf(R[8], pz, t[2])));
                hq[k] = 0.5f * fmaf(x, x, fmaf(y, y, z * z));
                nx[k] = pack2(-x, -x);
                ny[k] = pack2(-y, -y);
                nz[k] = pack2(-z, -z);
            }
        }

        float ma[QPT], mb[QPT];
        #pragma unroll
        for (int k = 0; k < QPT; k++) { ma[k] = INFINITY; mb[k] = INFINITY; }

        __syncthreads();

        const ulonglong2* __restrict__ axy = (const ulonglong2*)s_xy;
        const ulonglong2* __restrict__ azh = (const ulonglong2*)s_zh;

        #pragma unroll 4
        for (int j = 0; j < TILE_P; j++) {
            const ulonglong2 A = axy[j];   // (x0,x1) (y0,y1)
            const ulonglong2 B = azh[j];   // (z0,z1) (h0,h1)
            #pragma unroll
            for (int k = 0; k < QPT; k++) {
                ull v = fma2(nz[k], B.x, B.y);
                v = fma2(ny[k], A.y, v);
                v = fma2(nx[k], A.x, v);
                float lo, hi;
                unpack2(v, lo, hi);
                ma[k] = fminf(ma[k], lo);
                mb[k] = fminf(mb[k], hi);
            }
        }

        // exact deterministic min-combine: atomicMax on complement-encoding
        {
            const int db = dir * BB + b;
            #pragma unroll
            for (int k = 0; k < QPT; k++) {
                const unsigned int key = ~enc_f(fminf(ma[k], mb[k]) + hq[k]);
                atomicMax(&g_menc[db * NN + nbase + k * TPB], key);
            }
        }
    }
}

// ---------------------------------------------------------------------------
// Deterministic block sum reduction (valid in thread 0)
// ---------------------------------------------------------------------------
__device__ __forceinline__ float block_reduce_sum(float v)
{
    __shared__ float ws[TPB / 32];
    #pragma unroll
    for (int o = 16; o > 0; o >>= 1) v += __shfl_down_sync(0xffffffffu, v, o);
    if ((threadIdx.x & 31) == 0) ws[threadIdx.x >> 5] = v;
    __syncthreads();
    if (threadIdx.x < 32) {
        v = (threadIdx.x < TPB / 32) ? ws[threadIdx.x] : 0.f;
        #pragma unroll
        for (int o = 4; o > 0; o >>= 1) v += __shfl_down_sync(0xffffffffu, v, o);
    }
    return v;
}

// ---------------------------------------------------------------------------
// Kernel 2 (PDL secondary): loss_trans BEFORE the grid-dependency sync,
// then read+reset g_menc (one uint4/thread), deferred sqrt, fixed-order
// final sum in the last-done block. Also resets g_work for the next replay.
// ---------------------------------------------------------------------------
__global__ void __launch_bounds__(TPB) k_reduce(
    const float* __restrict__ pred_rot,   const float* __restrict__ pred_trans,
    const float* __restrict__ ctx_hyp_rot,const float* __restrict__ ctx_hyp_trans,
    const float* __restrict__ gt_rot,     const float* __restrict__ gt_trans,
    const float* __restrict__ ctx_gt_rot, const float* __restrict__ ctx_gt_trans,
    float* __restrict__ out)
{
    const int tid = threadIdx.x;

    // independent preamble: loss_trans in block 0 (overlaps chamfer tail)
    __shared__ float sR[2][BB][9];
    __shared__ float sT[2][BB][3];
    if (blockIdx.x == 0) {
        if (tid < 2 * BB)
            rel_transform_16(tid, pred_rot, pred_trans, ctx_hyp_rot, ctx_hyp_trans,
                             gt_rot, gt_trans, ctx_gt_rot, ctx_gt_trans, sR, sT);
        __syncthreads();
        if (tid == 0) {
            float lt = 0.f;
            #pragma unroll
            for (int bb = 0; bb < BB; bb++)
                #pragma unroll
                for (int i = 0; i < 3; i++)
                    lt += fabsf(sT[0][bb][i] - sT[1][bb][i]);
            out[1] = lt * (1.0f / (BB * 3));
        }
    }

    // wait for chamfer's writes to be visible
    cudaGridDependencySynchronize();

    // one uint4 per thread: 64 blk * 256 thr * 4 = 65536 slots
    const int i = blockIdx.x * TPB + tid;
    uint4* __restrict__ me4 = (uint4*)g_menc;
    const uint4 kv = __ldcg(&me4[i]);
    me4[i] = make_uint4(0u, 0u, 0u, 0u);     // reset for next replay
    float s = sqrtf(fmaxf(2.0f * dec_f(~kv.x), 0.0f))
            + sqrtf(fmaxf(2.0f * dec_f(~kv.y), 0.0f))
            + sqrtf(fmaxf(2.0f * dec_f(~kv.z), 0.0f))
            + sqrtf(fmaxf(2.0f * dec_f(~kv.w), 0.0f));

    float bs = block_reduce_sum(s);

    __shared__ bool is_last;
    if (tid == 0) {
        g_partials[blockIdx.x] = bs;
        __threadfence();
        is_last = (atomicAdd(&g_done, 1u) == NRED_BLK - 1);
    }
    __syncthreads();

    if (is_last) {
        const volatile float* vp = g_partials;
        float v = (tid < NRED_BLK) ? vp[tid] : 0.f;
        float tot = block_reduce_sum(v);
        if (tid == 0) {
            out[0] = tot * (1.0f / (BB * NN));
            g_work = 0;   // reset work counter for next replay
            g_done = 0;   // reset completion counter for next replay
        }
    }
}

// ---------------------------------------------------------------------------
extern "C" void kernel_launch(void* const* d_in, const int* in_sizes, int n_in,
                              void* d_out, int out_size)
{
    const float* pred_rot      = (const float*)d_in[0];
    const float* pred_trans    = (const float*)d_in[1];
    const float* ctx_hyp_rot   = (const float*)d_in[2];
    const float* ctx_hyp_trans = (const float*)d_in[3];
    const float* gt_rot        = (const float*)d_in[4];
    const float* gt_trans      = (const float*)d_in[5];
    const float* ctx_gt_rot    = (const float*)d_in[6];
    const float* ctx_gt_trans  = (const float*)d_in[7];
    const float* model_points  = (const float*)d_in[8];
    float* out = (float*)d_out;

    k_chamfer<<<NBLK_CH, TPB>>>(
        pred_rot, pred_trans, ctx_hyp_rot, ctx_hyp_trans,
        gt_rot, gt_trans, ctx_gt_rot, ctx_gt_trans, model_points);

    // PDL launch: overlap reduce's launch + loss_trans with the chamfer tail
    cudaLaunchConfig_t cfg = {};
    cfg.gridDim  = dim3(NRED_BLK, 1, 1);
    cfg.blockDim = dim3(TPB, 1, 1);
    cfg.dynamicSmemBytes = 0;
    cfg.stream = 0;
    cudaLaunchAttribute attrs[1];
    attrs[0].id = cudaLaunchAttributeProgrammaticStreamSerialization;
    attrs[0].val.programmaticStreamSerializationAllowed = 1;
    cfg.attrs = attrs;
    cfg.numAttrs = 1;
    cudaLaunchKernelEx(&cfg, k_reduce,
                       pred_rot, pred_trans, ctx_hyp_rot, ctx_hyp_trans,
                       gt_rot, gt_trans, ctx_gt_rot, ctx_gt_trans, out);
}